// round 1
// baseline (speedup 1.0000x reference)
#include <cuda_runtime.h>
#include <cstdint>

#define K_DIM 512
#define C_DIM 64
#define J_DIM 32
#define KC    16

// Scratch (no allocation allowed): B[k][c] = {inv_var, -2*mu*inv_var}, per-(j,c) fused constant.
__device__ float2 g_B[K_DIM * C_DIM];
__device__ float  g_colconst[C_DIM];
__device__ float  g_cjc[J_DIM * C_DIM];

// Packed fp32x2 FMA (sm_100+). One instruction does both dot products' k-step.
__device__ __forceinline__ float2 ffma2(float2 a, float2 b, float2 c) {
#if __CUDA_ARCH__ >= 1000
    float2 d;
    asm("fma.rn.f32x2 %0, %1, %2, %3;"
        : "=l"(reinterpret_cast<unsigned long long&>(d))
        : "l"(reinterpret_cast<unsigned long long&>(a)),
          "l"(reinterpret_cast<unsigned long long&>(b)),
          "l"(reinterpret_cast<unsigned long long&>(c)));
    return d;
#else
    return make_float2(fmaf(a.x, b.x, c.x), fmaf(a.y, b.y, c.y));
#endif
}

// ---------------------------------------------------------------------------
// Precompute 1: per-component B matrix and column constants.
// grid = C_DIM blocks (one per component c), 128 threads.
// colconst[c] = -0.5 * ( sum_k mu^2*inv_var + sum_k log_var + K*log(2*pi) )
// ---------------------------------------------------------------------------
__global__ void pre_b_kernel(const float* __restrict__ mu,
                             const float* __restrict__ log_var) {
    int c = blockIdx.x;
    int t = threadIdx.x;
    float s = 0.0f;
    for (int k = t; k < K_DIM; k += 128) {
        float lv = log_var[c * K_DIM + k];
        float iv = expf(-lv);
        float m  = mu[c * K_DIM + k];
        g_B[k * C_DIM + c] = make_float2(iv, -2.0f * m * iv);
        s += m * m * iv + lv;
    }
    __shared__ float sh[128];
    sh[t] = s;
    __syncthreads();
    for (int o = 64; o > 0; o >>= 1) {
        if (t < o) sh[t] += sh[t + o];
        __syncthreads();
    }
    if (t == 0)
        g_colconst[c] = -0.5f * (sh[0] + (float)K_DIM * 1.8378770664093453f);
}

// ---------------------------------------------------------------------------
// Precompute 2: cjc[j][c] = log(alpha*beta[c] + njk[j][c]) + colconst[c]
// ---------------------------------------------------------------------------
__global__ void pre_cjc_kernel(const float* __restrict__ beta,
                               const float* __restrict__ njk,
                               const float* __restrict__ alpha) {
    int idx = blockIdx.x * 1024 + threadIdx.x;
    if (idx < J_DIM * C_DIM) {
        int c = idx & (C_DIM - 1);
        g_cjc[idx] = logf(alpha[0] * beta[c] + njk[idx]) + g_colconst[c];
    }
}

// ---------------------------------------------------------------------------
// Main kernel: 128-row x 64-col tile per block, 256 threads, 8x4 per thread.
// Inner loop: one fma.rn.f32x2 per (row, col, k):  acc += {x^2, x} * {iv, -2*mu*iv}
// Fused epilogue: logits = -0.5*(acc.x+acc.y) + cjc[macro[row]][c]; row softmax.
// ---------------------------------------------------------------------------
__global__ __launch_bounds__(256, 2)
void icgmm_main_kernel(const float* __restrict__ x,
                       const int*  __restrict__ macro,
                       float* __restrict__ out,
                       int N) {
    __shared__ float2 as2[128][KC + 1];     // {x*x, x}, padded (17) to avoid conflicts
    __shared__ float2 Bs[KC][C_DIM];        // {inv_var, -2*mu*inv_var}
    __shared__ float  cjc_s[J_DIM * C_DIM];

    int tid = threadIdx.x;
    int tx = tid & 15;         // col group: cols tx*4 .. tx*4+3
    int ty = tid >> 4;         // row group: rows ty*8 .. ty*8+7
    int nbase = blockIdx.x * 128;

    for (int i = tid; i < J_DIM * C_DIM; i += 256) cjc_s[i] = g_cjc[i];

    float2 acc[8][4];
#pragma unroll
    for (int r = 0; r < 8; r++)
#pragma unroll
        for (int c = 0; c < 4; c++) acc[r][c] = make_float2(0.0f, 0.0f);

    for (int kc = 0; kc < K_DIM; kc += KC) {
        __syncthreads();
        // ---- load x tile (128 x 16) as float4, square once, store {x^2, x} ----
#pragma unroll
        for (int p = 0; p < 2; p++) {
            int fi  = tid + p * 256;       // float4 index 0..511
            int row = fi >> 2;
            int kq  = fi & 3;
            int grow = nbase + row;
            float4 v = make_float4(0.0f, 0.0f, 0.0f, 0.0f);
            if (grow < N)
                v = *reinterpret_cast<const float4*>(
                        x + (size_t)grow * K_DIM + kc + kq * 4);
            as2[row][kq * 4 + 0] = make_float2(v.x * v.x, v.x);
            as2[row][kq * 4 + 1] = make_float2(v.y * v.y, v.y);
            as2[row][kq * 4 + 2] = make_float2(v.z * v.z, v.z);
            as2[row][kq * 4 + 3] = make_float2(v.w * v.w, v.w);
        }
        // ---- load B tile (16 x 64 float2 = 8 KB, contiguous) ----
        {
            const float4* src = reinterpret_cast<const float4*>(g_B + kc * C_DIM);
            float4* dst = reinterpret_cast<float4*>(&Bs[0][0]);
            dst[tid]       = src[tid];
            dst[tid + 256] = src[tid + 256];
        }
        __syncthreads();

#pragma unroll
        for (int kk = 0; kk < KC; kk++) {
            float2 a[8];
#pragma unroll
            for (int r = 0; r < 8; r++) a[r] = as2[ty * 8 + r][kk];
            float4 b01 = *reinterpret_cast<const float4*>(&Bs[kk][tx * 4]);
            float4 b23 = *reinterpret_cast<const float4*>(&Bs[kk][tx * 4 + 2]);
            float2 b[4] = { make_float2(b01.x, b01.y), make_float2(b01.z, b01.w),
                            make_float2(b23.x, b23.y), make_float2(b23.z, b23.w) };
#pragma unroll
            for (int r = 0; r < 8; r++)
#pragma unroll
                for (int c = 0; c < 4; c++)
                    acc[r][c] = ffma2(a[r], b[c], acc[r][c]);
        }
    }

    // ---- fused epilogue: add constants, row softmax over 64 cols (16 lanes) ----
#pragma unroll
    for (int r = 0; r < 8; r++) {
        int row  = nbase + ty * 8 + r;
        int rowc = (row < N) ? row : (N - 1);
        int j = macro[rowc];
        const float* cj = &cjc_s[j * C_DIM + tx * 4];
        float l[4];
#pragma unroll
        for (int c = 0; c < 4; c++)
            l[c] = -0.5f * (acc[r][c].x + acc[r][c].y) + cj[c];

        float m = fmaxf(fmaxf(l[0], l[1]), fmaxf(l[2], l[3]));
#pragma unroll
        for (int o = 8; o > 0; o >>= 1)
            m = fmaxf(m, __shfl_xor_sync(0xffffffffu, m, o));

        float e[4];
        float s = 0.0f;
#pragma unroll
        for (int c = 0; c < 4; c++) { e[c] = __expf(l[c] - m); s += e[c]; }
#pragma unroll
        for (int o = 8; o > 0; o >>= 1)
            s += __shfl_xor_sync(0xffffffffu, s, o);

        float inv = __fdividef(1.0f, s);
        if (row < N) {
            float4 o4 = make_float4(e[0] * inv, e[1] * inv, e[2] * inv, e[3] * inv);
            *reinterpret_cast<float4*>(out + (size_t)row * C_DIM + tx * 4) = o4;
        }
    }
}

// ---------------------------------------------------------------------------
// Inputs (metadata order): x[N*512], mu[64*512], log_var[64*512], beta[64],
// njk[32*64], alpha[1], macrostate[N] (int32). Output: posterior [N*64] f32.
// ---------------------------------------------------------------------------
extern "C" void kernel_launch(void* const* d_in, const int* in_sizes, int n_in,
                              void* d_out, int out_size) {
    const float* x       = (const float*)d_in[0];
    const float* mu      = (const float*)d_in[1];
    const float* log_var = (const float*)d_in[2];
    const float* beta    = (const float*)d_in[3];
    const float* njk     = (const float*)d_in[4];
    const float* alpha   = (const float*)d_in[5];
    const int*   macro   = (const int*)d_in[6];
    int N = in_sizes[0] / K_DIM;

    pre_b_kernel<<<C_DIM, 128>>>(mu, log_var);
    pre_cjc_kernel<<<2, 1024>>>(beta, njk, alpha);
    icgmm_main_kernel<<<(N + 127) / 128, 256>>>(x, macro, (float*)d_out, N);
}

// round 3
// speedup vs baseline: 2.3084x; 2.3084x over previous
#include <cuda_runtime.h>
#include <cuda_fp16.h>
#include <cstdint>

#define K_DIM 512
#define C_DIM 64
#define J_DIM 32
#define NCHUNK 8          // 512/64 k-chunks
#define TILE_M 128
#define NT 256

// ---------------- device scratch ----------------
// B images: [chunk][sub][n=64][72 halves]  sub = {iv_hi, iv_lo, -2mu*iv_hi, -2mu*iv_lo}
// pad to 72 halves (144B rows) so scalar-LDS B fragments are bank-conflict-free.
__device__ __half g_Bimg[NCHUNK * 4 * 64 * 72];
__device__ float  g_colconst[C_DIM];
__device__ float  g_cjc[J_DIM * C_DIM];

// ---------------- smem layout (dynamic) ----------------
#define A_OFF       0                    // 4 subs x 128x64 fp16 (SW128) = 65536
#define B_OFF(b)    (65536 + (b) * 36864)  // double buffer, 36864 each
#define CJC_OFF     139264              // 2048 floats = 8192
#define SMEM_TOTAL  147456
#define LOG_STRIDE  66                  // logits row stride (floats); reuses A region

// ---------------- helpers ----------------
__device__ __forceinline__ uint32_t smem_u32(const void* p) {
    uint32_t a;
    asm("{ .reg .u64 t; cvta.to.shared.u64 t, %1; cvt.u32.u64 %0, t; }" : "=r"(a) : "l"(p));
    return a;
}
__device__ __forceinline__ uint32_t swz(uint32_t off) {   // SW128: XOR bits[4:6] with row%8
    return off ^ ((off >> 3) & 0x70);
}
__device__ __forceinline__ void ldsm_x4(uint32_t* r, uint32_t addr) {
    asm volatile("ldmatrix.sync.aligned.m8n8.x4.shared.b16 {%0,%1,%2,%3}, [%4];"
                 : "=r"(r[0]), "=r"(r[1]), "=r"(r[2]), "=r"(r[3]) : "r"(addr));
}
__device__ __forceinline__ void mma16816(float* c, const uint32_t* a, const uint32_t* b) {
    asm volatile("mma.sync.aligned.m16n8k16.row.col.f32.f16.f16.f32 "
                 "{%0,%1,%2,%3}, {%4,%5,%6,%7}, {%8,%9}, {%0,%1,%2,%3};"
                 : "+f"(c[0]), "+f"(c[1]), "+f"(c[2]), "+f"(c[3])
                 : "r"(a[0]), "r"(a[1]), "r"(a[2]), "r"(a[3]), "r"(b[0]), "r"(b[1]));
}
__device__ __forceinline__ void cp_async16(uint32_t dst, const void* src) {
    asm volatile("cp.async.cg.shared.global [%0], [%1], 16;" :: "r"(dst), "l"(src));
}
__device__ __forceinline__ void cp_commit() {
    asm volatile("cp.async.commit_group;" ::: "memory");
}
template <int N_>
__device__ __forceinline__ void cp_wait() {
    asm volatile("cp.async.wait_group %0;" :: "n"(N_) : "memory");
}

// ---------------------------------------------------------------------------
// Precompute: B images (fp16 hi/lo) + colconst
// ---------------------------------------------------------------------------
__global__ void pre_b_kernel(const float* __restrict__ mu,
                             const float* __restrict__ log_var) {
    int c = blockIdx.x;          // component 0..63
    int t = threadIdx.x;
    float s = 0.0f;
    for (int k = t; k < K_DIM; k += 128) {
        float lv = log_var[c * K_DIM + k];
        float iv = expf(-lv);
        float m  = mu[c * K_DIM + k];
        float w0 = iv;
        float w1 = -2.0f * m * iv;
        int chunk = k >> 6, kl = k & 63;
        __half h;
        size_t base = (size_t)chunk * 4 * 64 * 72 + (size_t)c * 72 + kl;
        h = __float2half_rn(w0);
        g_Bimg[base + 0 * 64 * 72] = h;
        g_Bimg[base + 1 * 64 * 72] = __float2half_rn(w0 - __half2float(h));
        h = __float2half_rn(w1);
        g_Bimg[base + 2 * 64 * 72] = h;
        g_Bimg[base + 3 * 64 * 72] = __float2half_rn(w1 - __half2float(h));
        s += m * m * iv + lv;
    }
    __shared__ float sh[128];
    sh[t] = s;
    __syncthreads();
    for (int o = 64; o > 0; o >>= 1) {
        if (t < o) sh[t] += sh[t + o];
        __syncthreads();
    }
    if (t == 0)
        g_colconst[c] = -0.5f * (sh[0] + (float)K_DIM * 1.8378770664093453f);
}

__global__ void pre_cjc_kernel(const float* __restrict__ beta,
                               const float* __restrict__ njk,
                               const float* __restrict__ alpha) {
    int idx = blockIdx.x * 1024 + threadIdx.x;
    if (idx < J_DIM * C_DIM) {
        int c = idx & (C_DIM - 1);
        g_cjc[idx] = logf(alpha[0] * beta[c] + njk[idx]) + g_colconst[c];
    }
}

// ---------------------------------------------------------------------------
// Main kernel
// ---------------------------------------------------------------------------
__global__ __launch_bounds__(NT, 1)
void icgmm_mma_kernel(const float* __restrict__ x,
                      const int*  __restrict__ macro,
                      float* __restrict__ out,
                      int N) {
    extern __shared__ char smem[];
    const uint32_t sb = smem_u32(smem);
    const int tid = threadIdx.x;
    const int wid = tid >> 5;
    const int lane = tid & 31;
    const int warp_m = wid >> 1;        // 0..3 -> rows warp_m*32
    const int warp_n = wid & 1;         // 0..1 -> cols warp_n*32
    const int nbase = blockIdx.x * TILE_M;

    // stage cjc table
    for (int i = tid; i < J_DIM * C_DIM; i += NT)
        *reinterpret_cast<float*>(smem + CJC_OFF + i * 4) = g_cjc[i];

    const float4* __restrict__ x4 = reinterpret_cast<const float4*>(x);

    float acc[2][4][4];
#pragma unroll
    for (int mt = 0; mt < 2; mt++)
#pragma unroll
        for (int nt = 0; nt < 4; nt++)
#pragma unroll
            for (int q = 0; q < 4; q++) acc[mt][nt][q] = 0.0f;

    // ---- preload: x chunk 0 into regs, B chunk 0 via cp.async ----
    float4 xv[8];
#pragma unroll
    for (int p = 0; p < 8; p++) {
        int fi = tid + p * 256;
        int row = fi >> 4, c4 = fi & 15;
        int grow = nbase + row;
        xv[p] = (grow < N) ? x4[(size_t)grow * 128 + c4]
                           : make_float4(0.f, 0.f, 0.f, 0.f);
    }
    {
        const char* src = reinterpret_cast<const char*>(g_Bimg);
#pragma unroll
        for (int p = 0; p < 9; p++) {
            int off = (tid + p * 256) * 16;
            cp_async16(sb + B_OFF(0) + off, src + off);
        }
        cp_commit();
    }

#pragma unroll 1
    for (int i = 0; i < NCHUNK; i++) {
        const int buf = i & 1;

        // ---- convert x -> {x2hi,x2lo,xhi,xlo} fp16, store SW128-swizzled ----
#pragma unroll
        for (int p = 0; p < 8; p++) {
            int fi = tid + p * 256;
            int row = fi >> 4, c4 = fi & 15;
            uint32_t aoff = swz((uint32_t)(row * 128 + c4 * 8));
            float4 v = xv[p];

            __half2 xh01 = __floats2half2_rn(v.x, v.y);
            __half2 xh23 = __floats2half2_rn(v.z, v.w);
            float2 f01 = __half22float2(xh01);
            float2 f23 = __half22float2(xh23);
            __half2 xl01 = __floats2half2_rn(v.x - f01.x, v.y - f01.y);
            __half2 xl23 = __floats2half2_rn(v.z - f23.x, v.w - f23.y);

            float sx = v.x * v.x, sy = v.y * v.y, sz = v.z * v.z, sw = v.w * v.w;
            __half2 sh01 = __floats2half2_rn(sx, sy);
            __half2 sh23 = __floats2half2_rn(sz, sw);
            float2 g01 = __half22float2(sh01);
            float2 g23 = __half22float2(sh23);
            __half2 sl01 = __floats2half2_rn(sx - g01.x, sy - g01.y);
            __half2 sl23 = __floats2half2_rn(sz - g23.x, sw - g23.y);

            uint2 u;
            u.x = reinterpret_cast<uint32_t&>(sh01);
            u.y = reinterpret_cast<uint32_t&>(sh23);
            *reinterpret_cast<uint2*>(smem + A_OFF + 0 * 16384 + aoff) = u;
            u.x = reinterpret_cast<uint32_t&>(sl01);
            u.y = reinterpret_cast<uint32_t&>(sl23);
            *reinterpret_cast<uint2*>(smem + A_OFF + 1 * 16384 + aoff) = u;
            u.x = reinterpret_cast<uint32_t&>(xh01);
            u.y = reinterpret_cast<uint32_t&>(xh23);
            *reinterpret_cast<uint2*>(smem + A_OFF + 2 * 16384 + aoff) = u;
            u.x = reinterpret_cast<uint32_t&>(xl01);
            u.y = reinterpret_cast<uint32_t&>(xl23);
            *reinterpret_cast<uint2*>(smem + A_OFF + 3 * 16384 + aoff) = u;
        }

        // ---- prefetch next B chunk via cp.async (double-buffered) ----
        if (i + 1 < NCHUNK) {
            const char* src = reinterpret_cast<const char*>(g_Bimg) + (i + 1) * 36864;
#pragma unroll
            for (int p = 0; p < 9; p++) {
                int off = (tid + p * 256) * 16;
                cp_async16(sb + B_OFF((i + 1) & 1) + off, src + off);
            }
        }
        cp_commit();
        cp_wait<1>();          // current chunk's B has landed
        __syncthreads();

        // ---- prefetch next x chunk into regs (hidden behind MMA) ----
        if (i + 1 < NCHUNK) {
#pragma unroll
            for (int p = 0; p < 8; p++) {
                int fi = tid + p * 256;
                int row = fi >> 4, c4 = fi & 15;
                int grow = nbase + row;
                xv[p] = (grow < N)
                      ? x4[(size_t)grow * 128 + (i + 1) * 16 + c4]
                      : make_float4(0.f, 0.f, 0.f, 0.f);
            }
        }

        // ---- MMA phase: 4 k16-steps x 2 features x 3 split-combos ----
#pragma unroll
        for (int k16 = 0; k16 < 4; k16++) {
#pragma unroll
            for (int f = 0; f < 2; f++) {
                uint32_t ah[2][4], al[2][4];
#pragma unroll
                for (int mt = 0; mt < 2; mt++) {
                    int row = warp_m * 32 + mt * 16 + (lane & 15);
                    uint32_t boff = swz((uint32_t)(row * 128 + k16 * 32 + (lane >> 4) * 16));
                    ldsm_x4(ah[mt], sb + A_OFF + (f * 2 + 0) * 16384 + boff);
                    ldsm_x4(al[mt], sb + A_OFF + (f * 2 + 1) * 16384 + boff);
                }
                uint32_t bh[4][2], bl[4][2];
#pragma unroll
                for (int nt = 0; nt < 4; nt++) {
                    int n = warp_n * 32 + nt * 8 + (lane >> 2);
                    uint32_t woff = (uint32_t)(n * 144 + k16 * 32 + (lane & 3) * 4);
                    const char* bbase = smem + B_OFF(buf);
                    bh[nt][0] = *reinterpret_cast<const uint32_t*>(bbase + (f * 2 + 0) * 9216 + woff);
                    bh[nt][1] = *reinterpret_cast<const uint32_t*>(bbase + (f * 2 + 0) * 9216 + woff + 16);
                    bl[nt][0] = *reinterpret_cast<const uint32_t*>(bbase + (f * 2 + 1) * 9216 + woff);
                    bl[nt][1] = *reinterpret_cast<const uint32_t*>(bbase + (f * 2 + 1) * 9216 + woff + 16);
                }
#pragma unroll
                for (int mt = 0; mt < 2; mt++)
#pragma unroll
                    for (int nt = 0; nt < 4; nt++) {
                        mma16816(acc[mt][nt], ah[mt], bh[nt]);
                        mma16816(acc[mt][nt], ah[mt], bl[nt]);
                        mma16816(acc[mt][nt], al[mt], bh[nt]);
                    }
            }
        }
        __syncthreads();   // A-buffer reads done before next chunk's stores
    }

    // ---- epilogue: accumulators -> smem logits -> fused softmax ----
    float* logits = reinterpret_cast<float*>(smem + A_OFF);
#pragma unroll
    for (int mt = 0; mt < 2; mt++)
#pragma unroll
        for (int nt = 0; nt < 4; nt++) {
            int r0 = warp_m * 32 + mt * 16 + (lane >> 2);
            int c0 = warp_n * 32 + nt * 8 + 2 * (lane & 3);
            *reinterpret_cast<float2*>(logits + r0 * LOG_STRIDE + c0) =
                make_float2(acc[mt][nt][0], acc[mt][nt][1]);
            *reinterpret_cast<float2*>(logits + (r0 + 8) * LOG_STRIDE + c0) =
                make_float2(acc[mt][nt][2], acc[mt][nt][3]);
        }
    __syncthreads();

    {
        int row  = tid >> 1;
        int half = tid & 1;
        int grow = nbase + row;
        int rowc = (grow < N) ? grow : (N - 1);
        int j = macro[rowc];
        const float* cj = reinterpret_cast<const float*>(smem + CJC_OFF) + j * C_DIM + half * 32;
        const float* lr = logits + row * LOG_STRIDE + half * 32;

        float l[32];
#pragma unroll
        for (int c = 0; c < 32; c++)
            l[c] = fmaf(-0.5f, lr[c], cj[c]);

        float mx = l[0];
#pragma unroll
        for (int c = 1; c < 32; c++) mx = fmaxf(mx, l[c]);
        mx = fmaxf(mx, __shfl_xor_sync(0xffffffffu, mx, 1));

        float s = 0.0f;
#pragma unroll
        for (int c = 0; c < 32; c++) { l[c] = __expf(l[c] - mx); s += l[c]; }
        s += __shfl_xor_sync(0xffffffffu, s, 1);

        float inv = __fdividef(1.0f, s);
        if (grow < N) {
            float4* o4 = reinterpret_cast<float4*>(out + (size_t)grow * C_DIM + half * 32);
#pragma unroll
            for (int q = 0; q < 8; q++)
                o4[q] = make_float4(l[q * 4] * inv, l[q * 4 + 1] * inv,
                                    l[q * 4 + 2] * inv, l[q * 4 + 3] * inv);
        }
    }
}

// ---------------------------------------------------------------------------
extern "C" void kernel_launch(void* const* d_in, const int* in_sizes, int n_in,
                              void* d_out, int out_size) {
    const float* x       = (const float*)d_in[0];
    const float* mu      = (const float*)d_in[1];
    const float* log_var = (const float*)d_in[2];
    const float* beta    = (const float*)d_in[3];
    const float* njk     = (const float*)d_in[4];
    const float* alpha   = (const float*)d_in[5];
    const int*   macro   = (const int*)d_in[6];
    int N = in_sizes[0] / K_DIM;

    static bool attr_set = false;
    if (!attr_set) {
        cudaFuncSetAttribute(icgmm_mma_kernel,
                             cudaFuncAttributeMaxDynamicSharedMemorySize, SMEM_TOTAL);
        attr_set = true;
    }

    pre_b_kernel<<<C_DIM, 128>>>(mu, log_var);
    pre_cjc_kernel<<<2, 1024>>>(beta, njk, alpha);
    icgmm_mma_kernel<<<(N + TILE_M - 1) / TILE_M, NT, SMEM_TOTAL>>>(
        x, macro, (float*)d_out, N);
}

// round 6
// speedup vs baseline: 2.3089x; 1.0002x over previous
#include <cuda_runtime.h>
#include <cuda_fp16.h>
#include <cstdint>

#define K_DIM 512
#define C_DIM 64
#define J_DIM 32
#define NCHUNK 8
#define TILE_M 128
#define NT 256

// ---------------- device scratch ----------------
// B images: [chunk][sub=4][n=64][72 halves]; subs = {iv_hi, iv_lo, -2mu*iv_hi, -2mu*iv_lo}
__device__ __half g_Bimg[NCHUNK * 4 * 64 * 72];
__device__ float  g_colconst[C_DIM];
__device__ float  g_cjc[J_DIM * C_DIM];

// ---------------- smem layout ----------------
// A: 2 bufs x 3 subs x 16KB = 98304   subs = {x2_hi, x_hi, x_lo}
// B: 2 bufs x 36864 = 73728
#define A_OFF(b, s) ((b) * 49152 + (s) * 16384)
#define B_OFF(b)    (98304 + (b) * 36864)
#define SMEM_TOTAL  172032
#define LOG_STRIDE  66

// ---------------- helpers ----------------
__device__ __forceinline__ uint32_t smem_u32(const void* p) {
    uint32_t a;
    asm("{ .reg .u64 t; cvta.to.shared.u64 t, %1; cvt.u32.u64 %0, t; }" : "=r"(a) : "l"(p));
    return a;
}
__device__ __forceinline__ uint32_t swz(uint32_t off) {
    return off ^ ((off >> 3) & 0x70);
}
__device__ __forceinline__ void ldsm_x4(uint32_t* r, uint32_t addr) {
    asm volatile("ldmatrix.sync.aligned.m8n8.x4.shared.b16 {%0,%1,%2,%3}, [%4];"
                 : "=r"(r[0]), "=r"(r[1]), "=r"(r[2]), "=r"(r[3]) : "r"(addr));
}
__device__ __forceinline__ void mma16816(float* c, const uint32_t* a, const uint32_t* b) {
    asm volatile("mma.sync.aligned.m16n8k16.row.col.f32.f16.f16.f32 "
                 "{%0,%1,%2,%3}, {%4,%5,%6,%7}, {%8,%9}, {%0,%1,%2,%3};"
                 : "+f"(c[0]), "+f"(c[1]), "+f"(c[2]), "+f"(c[3])
                 : "r"(a[0]), "r"(a[1]), "r"(a[2]), "r"(a[3]), "r"(b[0]), "r"(b[1]));
}
__device__ __forceinline__ void cp_async16(uint32_t dst, const void* src) {
    asm volatile("cp.async.cg.shared.global [%0], [%1], 16;" :: "r"(dst), "l"(src));
}
__device__ __forceinline__ void cp_commit() {
    asm volatile("cp.async.commit_group;" ::: "memory");
}
template <int N_>
__device__ __forceinline__ void cp_wait() {
    asm volatile("cp.async.wait_group %0;" :: "n"(N_) : "memory");
}

// ---------------------------------------------------------------------------
__global__ void pre_b_kernel(const float* __restrict__ mu,
                             const float* __restrict__ log_var) {
    int c = blockIdx.x;
    int t = threadIdx.x;
    float s = 0.0f;
    for (int k = t; k < K_DIM; k += 128) {
        float lv = log_var[c * K_DIM + k];
        float iv = expf(-lv);
        float m  = mu[c * K_DIM + k];
        float w0 = iv;
        float w1 = -2.0f * m * iv;
        int chunk = k >> 6, kl = k & 63;
        __half h;
        size_t base = (size_t)chunk * 4 * 64 * 72 + (size_t)c * 72 + kl;
        h = __float2half_rn(w0);
        g_Bimg[base + 0 * 64 * 72] = h;
        g_Bimg[base + 1 * 64 * 72] = __float2half_rn(w0 - __half2float(h));
        h = __float2half_rn(w1);
        g_Bimg[base + 2 * 64 * 72] = h;
        g_Bimg[base + 3 * 64 * 72] = __float2half_rn(w1 - __half2float(h));
        s += m * m * iv + lv;
    }
    __shared__ float sh[128];
    sh[t] = s;
    __syncthreads();
    for (int o = 64; o > 0; o >>= 1) {
        if (t < o) sh[t] += sh[t + o];
        __syncthreads();
    }
    if (t == 0)
        g_colconst[c] = -0.5f * (sh[0] + (float)K_DIM * 1.8378770664093453f);
}

__global__ void pre_cjc_kernel(const float* __restrict__ beta,
                               const float* __restrict__ njk,
                               const float* __restrict__ alpha) {
    int idx = blockIdx.x * 1024 + threadIdx.x;
    if (idx < J_DIM * C_DIM) {
        int c = idx & (C_DIM - 1);
        g_cjc[idx] = logf(alpha[0] * beta[c] + njk[idx]) + g_colconst[c];
    }
}

// convert quarter q of a chunk: thread handles row=(tid+q*256)>>3, 8 floats
__device__ __forceinline__ void convert_quarter(char* smem, int nbuf, int q,
                                                const float4* xv, int tid) {
    int fi = tid + q * 256;
    int row = fi >> 3, g8 = fi & 7;
    uint32_t aoff = swz((uint32_t)(row * 128 + g8 * 16));
    float4 v0 = xv[2 * q], v1 = xv[2 * q + 1];

    // x^2 (single fp16 digit)
    float s0 = v0.x * v0.x, s1 = v0.y * v0.y, s2 = v0.z * v0.z, s3 = v0.w * v0.w;
    float s4 = v1.x * v1.x, s5 = v1.y * v1.y, s6 = v1.z * v1.z, s7 = v1.w * v1.w;
    __half2 q0 = __floats2half2_rn(s0, s1), q1 = __floats2half2_rn(s2, s3);
    __half2 q2 = __floats2half2_rn(s4, s5), q3 = __floats2half2_rn(s6, s7);
    uint4 u;
    u.x = reinterpret_cast<uint32_t&>(q0); u.y = reinterpret_cast<uint32_t&>(q1);
    u.z = reinterpret_cast<uint32_t&>(q2); u.w = reinterpret_cast<uint32_t&>(q3);
    *reinterpret_cast<uint4*>(smem + A_OFF(nbuf, 0) + aoff) = u;

    // x hi
    __half2 h0 = __floats2half2_rn(v0.x, v0.y), h1 = __floats2half2_rn(v0.z, v0.w);
    __half2 h2 = __floats2half2_rn(v1.x, v1.y), h3 = __floats2half2_rn(v1.z, v1.w);
    u.x = reinterpret_cast<uint32_t&>(h0); u.y = reinterpret_cast<uint32_t&>(h1);
    u.z = reinterpret_cast<uint32_t&>(h2); u.w = reinterpret_cast<uint32_t&>(h3);
    *reinterpret_cast<uint4*>(smem + A_OFF(nbuf, 1) + aoff) = u;

    // x lo
    float2 f0 = __half22float2(h0), f1 = __half22float2(h1);
    float2 f2 = __half22float2(h2), f3 = __half22float2(h3);
    __half2 l0 = __floats2half2_rn(v0.x - f0.x, v0.y - f0.y);
    __half2 l1 = __floats2half2_rn(v0.z - f1.x, v0.w - f1.y);
    __half2 l2 = __floats2half2_rn(v1.x - f2.x, v1.y - f2.y);
    __half2 l3 = __floats2half2_rn(v1.z - f3.x, v1.w - f3.y);
    u.x = reinterpret_cast<uint32_t&>(l0); u.y = reinterpret_cast<uint32_t&>(l1);
    u.z = reinterpret_cast<uint32_t&>(l2); u.w = reinterpret_cast<uint32_t&>(l3);
    *reinterpret_cast<uint4*>(smem + A_OFF(nbuf, 2) + aoff) = u;
}

__device__ __forceinline__ void load_xv(float4* xv, const float4* __restrict__ x4,
                                        int nbase, int chunk, int tid, int N) {
#pragma unroll
    for (int q = 0; q < 4; q++) {
        int fi = tid + q * 256;
        int row = fi >> 3, g8 = fi & 7;
        int grow = nbase + row;
        if (grow < N) {
            size_t idx = (size_t)grow * 128 + chunk * 16 + g8 * 2;
            xv[2 * q]     = x4[idx];
            xv[2 * q + 1] = x4[idx + 1];
        } else {
            xv[2 * q]     = make_float4(0.f, 0.f, 0.f, 0.f);
            xv[2 * q + 1] = make_float4(0.f, 0.f, 0.f, 0.f);
        }
    }
}

// ---------------------------------------------------------------------------
__global__ __launch_bounds__(NT, 1)
void icgmm_mma_kernel(const float* __restrict__ x,
                      const int*  __restrict__ macro,
                      float* __restrict__ out,
                      int N) {
    extern __shared__ char smem[];
    const uint32_t sb = smem_u32(smem);
    const int tid = threadIdx.x;
    const int wid = tid >> 5;
    const int lane = tid & 31;
    const int warp_m = wid >> 1;
    const int warp_n = wid & 1;
    const int nbase = blockIdx.x * TILE_M;

    const float4* __restrict__ x4 = reinterpret_cast<const float4*>(x);

    float acc[2][4][4];
#pragma unroll
    for (int mt = 0; mt < 2; mt++)
#pragma unroll
        for (int nt = 0; nt < 4; nt++)
#pragma unroll
            for (int q = 0; q < 4; q++) acc[mt][nt][q] = 0.0f;

    float4 xv[8];

    // ---- prologue: B(0) via cp.async; xv(0) load; convert chunk 0 -> buf0 ----
    {
        const char* src = reinterpret_cast<const char*>(g_Bimg);
#pragma unroll
        for (int p = 0; p < 9; p++) {
            int off = (tid + p * 256) * 16;
            cp_async16(sb + B_OFF(0) + off, src + off);
        }
        cp_commit();
    }
    load_xv(xv, x4, nbase, 0, tid, N);
#pragma unroll
    for (int q = 0; q < 4; q++) convert_quarter(smem, 0, q, xv, tid);

#pragma unroll 1
    for (int i = 0; i < NCHUNK; i++) {
        const int buf = i & 1;
        const int nbuf = buf ^ 1;
        const bool has_next = (i + 1 < NCHUNK);

        cp_wait<0>();          // B(i) landed (only group outstanding here)
        __syncthreads();       // A(i) visible; prior readers of nbuf slots done

        // prefetch B(i+1) AFTER the wait point, so it stays in flight under MMA
        if (has_next) {
            const char* src = reinterpret_cast<const char*>(g_Bimg) + (i + 1) * 36864;
#pragma unroll
            for (int p = 0; p < 9; p++) {
                int off = (tid + p * 256) * 16;
                cp_async16(sb + B_OFF(nbuf) + off, src + off);
            }
            cp_commit();
            // prefetch x(i+1) into registers (consumed by convert quarters below)
            load_xv(xv, x4, nbase, i + 1, tid, N);
        }

        // ---- MMA chunk i, interleaved with convert of chunk i+1 ----
#pragma unroll
        for (int k16 = 0; k16 < 4; k16++) {
            uint32_t a2[2][4], ah[2][4], al[2][4];
#pragma unroll
            for (int mt = 0; mt < 2; mt++) {
                int row = warp_m * 32 + mt * 16 + (lane & 15);
                uint32_t boff = swz((uint32_t)(row * 128 + k16 * 32 + (lane >> 4) * 16));
                ldsm_x4(a2[mt], sb + A_OFF(buf, 0) + boff);
                ldsm_x4(ah[mt], sb + A_OFF(buf, 1) + boff);
                ldsm_x4(al[mt], sb + A_OFF(buf, 2) + boff);
            }
#pragma unroll
            for (int nt = 0; nt < 4; nt++) {
                int n = warp_n * 32 + nt * 8 + (lane >> 2);
                uint32_t woff = (uint32_t)(n * 144 + k16 * 32 + (lane & 3) * 4);
                const char* bbase = smem + B_OFF(buf);
                uint32_t bivh[2], bivl[2], bmh[2], bml[2];
                bivh[0] = *reinterpret_cast<const uint32_t*>(bbase + 0 * 9216 + woff);
                bivh[1] = *reinterpret_cast<const uint32_t*>(bbase + 0 * 9216 + woff + 16);
                bivl[0] = *reinterpret_cast<const uint32_t*>(bbase + 1 * 9216 + woff);
                bivl[1] = *reinterpret_cast<const uint32_t*>(bbase + 1 * 9216 + woff + 16);
                bmh[0]  = *reinterpret_cast<const uint32_t*>(bbase + 2 * 9216 + woff);
                bmh[1]  = *reinterpret_cast<const uint32_t*>(bbase + 2 * 9216 + woff + 16);
                bml[0]  = *reinterpret_cast<const uint32_t*>(bbase + 3 * 9216 + woff);
                bml[1]  = *reinterpret_cast<const uint32_t*>(bbase + 3 * 9216 + woff + 16);
#pragma unroll
                for (int mt = 0; mt < 2; mt++) {
                    mma16816(acc[mt][nt], a2[mt], bivh);   // x2h * iv_hi
                    mma16816(acc[mt][nt], a2[mt], bivl);   // x2h * iv_lo
                    mma16816(acc[mt][nt], ah[mt], bmh);    // xh * m_hi
                    mma16816(acc[mt][nt], ah[mt], bml);    // xh * m_lo
                    mma16816(acc[mt][nt], al[mt], bmh);    // xl * m_hi
                }
            }
            // interleave: convert quarter k16 of chunk i+1 into nbuf
            if (has_next) convert_quarter(smem, nbuf, k16, xv, tid);
        }
    }

    // ---- epilogue ----
    float* logits = reinterpret_cast<float*>(smem + A_OFF(0, 0));
#pragma unroll
    for (int mt = 0; mt < 2; mt++)
#pragma unroll
        for (int nt = 0; nt < 4; nt++) {
            int r0 = warp_m * 32 + mt * 16 + (lane >> 2);
            int c0 = warp_n * 32 + nt * 8 + 2 * (lane & 3);
            *reinterpret_cast<float2*>(logits + r0 * LOG_STRIDE + c0) =
                make_float2(acc[mt][nt][0], acc[mt][nt][1]);
            *reinterpret_cast<float2*>(logits + (r0 + 8) * LOG_STRIDE + c0) =
                make_float2(acc[mt][nt][2], acc[mt][nt][3]);
        }
    __syncthreads();

    {
        int row  = tid >> 1;
        int half = tid & 1;
        int grow = nbase + row;
        int rowc = (grow < N) ? grow : (N - 1);
        int j = macro[rowc];
        const float* cj = g_cjc + j * C_DIM + half * 32;
        const float* lr = logits + row * LOG_STRIDE + half * 32;

        float l[32];
#pragma unroll
        for (int c = 0; c < 32; c++)
            l[c] = fmaf(-0.5f, lr[c], __ldg(cj + c));

        float mx = l[0];
#pragma unroll
        for (int c = 1; c < 32; c++) mx = fmaxf(mx, l[c]);
        mx = fmaxf(mx, __shfl_xor_sync(0xffffffffu, mx, 1));

        float s = 0.0f;
#pragma unroll
        for (int c = 0; c < 32; c++) { l[c] = __expf(l[c] - mx); s += l[c]; }
        s += __shfl_xor_sync(0xffffffffu, s, 1);

        float inv = __fdividef(1.0f, s);
        if (grow < N) {
            float4* o4 = reinterpret_cast<float4*>(out + (size_t)grow * C_DIM + half * 32);
#pragma unroll
            for (int q = 0; q < 8; q++)
                o4[q] = make_float4(l[q * 4] * inv, l[q * 4 + 1] * inv,
                                    l[q * 4 + 2] * inv, l[q * 4 + 3] * inv);
        }
    }
}

// ---------------------------------------------------------------------------
extern "C" void kernel_launch(void* const* d_in, const int* in_sizes, int n_in,
                              void* d_out, int out_size) {
    const float* x       = (const float*)d_in[0];
    const float* mu      = (const float*)d_in[1];
    const float* log_var = (const float*)d_in[2];
    const float* beta    = (const float*)d_in[3];
    const float* njk     = (const float*)d_in[4];
    const float* alpha   = (const float*)d_in[5];
    const int*   macro   = (const int*)d_in[6];
    int N = in_sizes[0] / K_DIM;

    static bool attr_set = false;
    if (!attr_set) {
        cudaFuncSetAttribute(icgmm_mma_kernel,
                             cudaFuncAttributeMaxDynamicSharedMemorySize, SMEM_TOTAL);
        attr_set = true;
    }

    pre_b_kernel<<<C_DIM, 128>>>(mu, log_var);
    pre_cjc_kernel<<<2, 1024>>>(beta, njk, alpha);
    icgmm_mma_kernel<<<(N + TILE_M - 1) / TILE_M, NT, SMEM_TOTAL>>>(
        x, macro, (float*)d_out, N);
}

// round 9
// speedup vs baseline: 2.4626x; 1.0666x over previous
#include <cuda_runtime.h>
#include <cuda_fp16.h>
#include <cstdint>

#define K_DIM 512
#define C_DIM 64
#define J_DIM 32
#define NCHUNK 8
#define TILE_M 128
#define NT 256

// ---------------- device scratch ----------------
// B images: [chunk][sub=4][n=64][72 halves]; subs = {iv_hi, iv_lo, -2mu*iv_hi, -2mu*iv_lo}
__device__ __half g_Bimg[NCHUNK * 4 * 64 * 72];
__device__ float  g_cjc[J_DIM * C_DIM];

// ---------------- smem layout ----------------
// A: 2 bufs x 3 subs x 16KB = 98304   subs = {x2_hi, x_hi, x_lo}
// B: 2 bufs x 36864 = 73728
#define A_OFF(b, s) ((b) * 49152 + (s) * 16384)
#define B_OFF(b)    (98304 + (b) * 36864)
#define SMEM_TOTAL  172032
#define LOG_STRIDE  66

// ---------------- helpers ----------------
__device__ __forceinline__ uint32_t smem_u32(const void* p) {
    uint32_t a;
    asm("{ .reg .u64 t; cvta.to.shared.u64 t, %1; cvt.u32.u64 %0, t; }" : "=r"(a) : "l"(p));
    return a;
}
__device__ __forceinline__ uint32_t swz(uint32_t off) {
    return off ^ ((off >> 3) & 0x70);
}
__device__ __forceinline__ void ldsm_x4(uint32_t* r, uint32_t addr) {
    asm volatile("ldmatrix.sync.aligned.m8n8.x4.shared.b16 {%0,%1,%2,%3}, [%4];"
                 : "=r"(r[0]), "=r"(r[1]), "=r"(r[2]), "=r"(r[3]) : "r"(addr));
}
__device__ __forceinline__ void mma16816(float* c, const uint32_t* a, const uint32_t* b) {
    asm volatile("mma.sync.aligned.m16n8k16.row.col.f32.f16.f16.f32 "
                 "{%0,%1,%2,%3}, {%4,%5,%6,%7}, {%8,%9}, {%0,%1,%2,%3};"
                 : "+f"(c[0]), "+f"(c[1]), "+f"(c[2]), "+f"(c[3])
                 : "r"(a[0]), "r"(a[1]), "r"(a[2]), "r"(a[3]), "r"(b[0]), "r"(b[1]));
}
__device__ __forceinline__ void cp_async16(uint32_t dst, const void* src) {
    asm volatile("cp.async.cg.shared.global [%0], [%1], 16;" :: "r"(dst), "l"(src));
}
__device__ __forceinline__ void cp_commit() {
    asm volatile("cp.async.commit_group;" ::: "memory");
}
template <int N_>
__device__ __forceinline__ void cp_wait() {
    asm volatile("cp.async.wait_group %0;" :: "n"(N_) : "memory");
}

// ---------------------------------------------------------------------------
// Merged precompute: block c builds B image rows for component c, colconst[c],
// and cjc[j][c] for all j.  ONE launch -> 2 launches per kernel_launch call,
// so ncu -s 5 -c 1 captures the MAIN kernel (pre0 main0 pre1 main1 pre2 MAIN2).
// ---------------------------------------------------------------------------
__global__ void pre_kernel(const float* __restrict__ mu,
                           const float* __restrict__ log_var,
                           const float* __restrict__ beta,
                           const float* __restrict__ njk,
                           const float* __restrict__ alpha) {
    int c = blockIdx.x;
    int t = threadIdx.x;
    float s = 0.0f;
    for (int k = t; k < K_DIM; k += 128) {
        float lv = log_var[c * K_DIM + k];
        float iv = expf(-lv);
        float m  = mu[c * K_DIM + k];
        float w0 = iv;
        float w1 = -2.0f * m * iv;
        int chunk = k >> 6, kl = k & 63;
        __half h;
        size_t base = (size_t)chunk * 4 * 64 * 72 + (size_t)c * 72 + kl;
        h = __float2half_rn(w0);
        g_Bimg[base + 0 * 64 * 72] = h;
        g_Bimg[base + 1 * 64 * 72] = __float2half_rn(w0 - __half2float(h));
        h = __float2half_rn(w1);
        g_Bimg[base + 2 * 64 * 72] = h;
        g_Bimg[base + 3 * 64 * 72] = __float2half_rn(w1 - __half2float(h));
        s += m * m * iv + lv;
    }
    __shared__ float sh[128];
    sh[t] = s;
    __syncthreads();
    for (int o = 64; o > 0; o >>= 1) {
        if (t < o) sh[t] += sh[t + o];
        __syncthreads();
    }
    float cc = -0.5f * (sh[0] + (float)K_DIM * 1.8378770664093453f);
    if (t < J_DIM)
        g_cjc[t * C_DIM + c] = logf(alpha[0] * beta[c] + njk[t * C_DIM + c]) + cc;
}

// convert quarter q of a chunk: thread handles row=(tid+q*256)>>3, 8 floats
__device__ __forceinline__ void convert_quarter(char* smem, int nbuf, int q,
                                                const float4* xv, int tid) {
    int fi = tid + q * 256;
    int row = fi >> 3, g8 = fi & 7;
    uint32_t aoff = swz((uint32_t)(row * 128 + g8 * 16));
    float4 v0 = xv[2 * q], v1 = xv[2 * q + 1];

    // x^2 (single fp16 digit)
    float s0 = v0.x * v0.x, s1 = v0.y * v0.y, s2 = v0.z * v0.z, s3 = v0.w * v0.w;
    float s4 = v1.x * v1.x, s5 = v1.y * v1.y, s6 = v1.z * v1.z, s7 = v1.w * v1.w;
    __half2 q0 = __floats2half2_rn(s0, s1), q1 = __floats2half2_rn(s2, s3);
    __half2 q2 = __floats2half2_rn(s4, s5), q3 = __floats2half2_rn(s6, s7);
    uint4 u;
    u.x = reinterpret_cast<uint32_t&>(q0); u.y = reinterpret_cast<uint32_t&>(q1);
    u.z = reinterpret_cast<uint32_t&>(q2); u.w = reinterpret_cast<uint32_t&>(q3);
    *reinterpret_cast<uint4*>(smem + A_OFF(nbuf, 0) + aoff) = u;

    // x hi
    __half2 h0 = __floats2half2_rn(v0.x, v0.y), h1 = __floats2half2_rn(v0.z, v0.w);
    __half2 h2 = __floats2half2_rn(v1.x, v1.y), h3 = __floats2half2_rn(v1.z, v1.w);
    u.x = reinterpret_cast<uint32_t&>(h0); u.y = reinterpret_cast<uint32_t&>(h1);
    u.z = reinterpret_cast<uint32_t&>(h2); u.w = reinterpret_cast<uint32_t&>(h3);
    *reinterpret_cast<uint4*>(smem + A_OFF(nbuf, 1) + aoff) = u;

    // x lo
    float2 f0 = __half22float2(h0), f1 = __half22float2(h1);
    float2 f2 = __half22float2(h2), f3 = __half22float2(h3);
    __half2 l0 = __floats2half2_rn(v0.x - f0.x, v0.y - f0.y);
    __half2 l1 = __floats2half2_rn(v0.z - f1.x, v0.w - f1.y);
    __half2 l2 = __floats2half2_rn(v1.x - f2.x, v1.y - f2.y);
    __half2 l3 = __floats2half2_rn(v1.z - f3.x, v1.w - f3.y);
    u.x = reinterpret_cast<uint32_t&>(l0); u.y = reinterpret_cast<uint32_t&>(l1);
    u.z = reinterpret_cast<uint32_t&>(l2); u.w = reinterpret_cast<uint32_t&>(l3);
    *reinterpret_cast<uint4*>(smem + A_OFF(nbuf, 2) + aoff) = u;
}

__device__ __forceinline__ void load_xv(float4* xv, const float4* __restrict__ x4,
                                        int nbase, int chunk, int tid, int N) {
#pragma unroll
    for (int q = 0; q < 4; q++) {
        int fi = tid + q * 256;
        int row = fi >> 3, g8 = fi & 7;
        int grow = nbase + row;
        if (grow < N) {
            size_t idx = (size_t)grow * 128 + chunk * 16 + g8 * 2;
            xv[2 * q]     = x4[idx];
            xv[2 * q + 1] = x4[idx + 1];
        } else {
            xv[2 * q]     = make_float4(0.f, 0.f, 0.f, 0.f);
            xv[2 * q + 1] = make_float4(0.f, 0.f, 0.f, 0.f);
        }
    }
}

// ---------------------------------------------------------------------------
__global__ __launch_bounds__(NT, 1)
void icgmm_mma_kernel(const float* __restrict__ x,
                      const int*  __restrict__ macro,
                      float* __restrict__ out,
                      int N) {
    extern __shared__ char smem[];
    const uint32_t sb = smem_u32(smem);
    const int tid = threadIdx.x;
    const int wid = tid >> 5;
    const int lane = tid & 31;
    const int warp_m = wid >> 1;
    const int warp_n = wid & 1;
    const int nbase = blockIdx.x * TILE_M;

    const float4* __restrict__ x4 = reinterpret_cast<const float4*>(x);

    float acc[2][4][4];
#pragma unroll
    for (int mt = 0; mt < 2; mt++)
#pragma unroll
        for (int nt = 0; nt < 4; nt++)
#pragma unroll
            for (int q = 0; q < 4; q++) acc[mt][nt][q] = 0.0f;

    float4 xv[8];

    // ---- prologue: B(0) via cp.async; xv(0) load; convert chunk 0 -> buf0 ----
    {
        const char* src = reinterpret_cast<const char*>(g_Bimg);
#pragma unroll
        for (int p = 0; p < 9; p++) {
            int off = (tid + p * 256) * 16;
            cp_async16(sb + B_OFF(0) + off, src + off);
        }
        cp_commit();
    }
    load_xv(xv, x4, nbase, 0, tid, N);
#pragma unroll
    for (int q = 0; q < 4; q++) convert_quarter(smem, 0, q, xv, tid);

#pragma unroll 1
    for (int i = 0; i < NCHUNK; i++) {
        const int buf = i & 1;
        const int nbuf = buf ^ 1;
        const bool has_next = (i + 1 < NCHUNK);

        // issue x(i+1) LDGs FIRST: consumed only at k16=2 of the MMA loop below,
        // giving ~2000+ cycles of latency cover.
        if (has_next) load_xv(xv, x4, nbase, i + 1, tid, N);

        cp_wait<0>();          // B(i) landed (only group outstanding here)
        __syncthreads();       // A(i) visible; prior readers of nbuf slots done

        // prefetch B(i+1) AFTER the wait point, so it stays in flight under MMA
        if (has_next) {
            const char* src = reinterpret_cast<const char*>(g_Bimg) + (i + 1) * 36864;
#pragma unroll
            for (int p = 0; p < 9; p++) {
                int off = (tid + p * 256) * 16;
                cp_async16(sb + B_OFF(nbuf) + off, src + off);
            }
            cp_commit();
        }

        // ---- MMA chunk i; converts of chunk i+1 happen at k16 = 2 and 3 ----
#pragma unroll
        for (int k16 = 0; k16 < 4; k16++) {
            uint32_t a2[2][4], ah[2][4], al[2][4];
#pragma unroll
            for (int mt = 0; mt < 2; mt++) {
                int row = warp_m * 32 + mt * 16 + (lane & 15);
                uint32_t boff = swz((uint32_t)(row * 128 + k16 * 32 + (lane >> 4) * 16));
                ldsm_x4(a2[mt], sb + A_OFF(buf, 0) + boff);
                ldsm_x4(ah[mt], sb + A_OFF(buf, 1) + boff);
                ldsm_x4(al[mt], sb + A_OFF(buf, 2) + boff);
            }
#pragma unroll
            for (int nt = 0; nt < 4; nt++) {
                int n = warp_n * 32 + nt * 8 + (lane >> 2);
                uint32_t woff = (uint32_t)(n * 144 + k16 * 32 + (lane & 3) * 4);
                const char* bbase = smem + B_OFF(buf);
                uint32_t bivh[2], bivl[2], bmh[2], bml[2];
                bivh[0] = *reinterpret_cast<const uint32_t*>(bbase + 0 * 9216 + woff);
                bivh[1] = *reinterpret_cast<const uint32_t*>(bbase + 0 * 9216 + woff + 16);
                bivl[0] = *reinterpret_cast<const uint32_t*>(bbase + 1 * 9216 + woff);
                bivl[1] = *reinterpret_cast<const uint32_t*>(bbase + 1 * 9216 + woff + 16);
                bmh[0]  = *reinterpret_cast<const uint32_t*>(bbase + 2 * 9216 + woff);
                bmh[1]  = *reinterpret_cast<const uint32_t*>(bbase + 2 * 9216 + woff + 16);
                bml[0]  = *reinterpret_cast<const uint32_t*>(bbase + 3 * 9216 + woff);
                bml[1]  = *reinterpret_cast<const uint32_t*>(bbase + 3 * 9216 + woff + 16);
                // combo-major, mt inner: same-acc MMAs spaced by 2
#pragma unroll
                for (int mt = 0; mt < 2; mt++) mma16816(acc[mt][nt], a2[mt], bivh);
#pragma unroll
                for (int mt = 0; mt < 2; mt++) mma16816(acc[mt][nt], a2[mt], bivl);
#pragma unroll
                for (int mt = 0; mt < 2; mt++) mma16816(acc[mt][nt], ah[mt], bmh);
#pragma unroll
                for (int mt = 0; mt < 2; mt++) mma16816(acc[mt][nt], ah[mt], bml);
#pragma unroll
                for (int mt = 0; mt < 2; mt++) mma16816(acc[mt][nt], al[mt], bmh);
            }
            // converts pushed late so x(i+1) LDGs have landed
            if (has_next && k16 >= 2) {
                convert_quarter(smem, nbuf, (k16 - 2) * 2 + 0, xv, tid);
                convert_quarter(smem, nbuf, (k16 - 2) * 2 + 1, xv, tid);
            }
        }
    }

    // ---- epilogue ----
    float* logits = reinterpret_cast<float*>(smem + A_OFF(0, 0));
#pragma unroll
    for (int mt = 0; mt < 2; mt++)
#pragma unroll
        for (int nt = 0; nt < 4; nt++) {
            int r0 = warp_m * 32 + mt * 16 + (lane >> 2);
            int c0 = warp_n * 32 + nt * 8 + 2 * (lane & 3);
            *reinterpret_cast<float2*>(logits + r0 * LOG_STRIDE + c0) =
                make_float2(acc[mt][nt][0], acc[mt][nt][1]);
            *reinterpret_cast<float2*>(logits + (r0 + 8) * LOG_STRIDE + c0) =
                make_float2(acc[mt][nt][2], acc[mt][nt][3]);
        }
    __syncthreads();

    {
        int row  = tid >> 1;
        int half = tid & 1;
        int grow = nbase + row;
        int rowc = (grow < N) ? grow : (N - 1);
        int j = macro[rowc];
        const float* cj = g_cjc + j * C_DIM + half * 32;
        const float* lr = logits + row * LOG_STRIDE + half * 32;

        float l[32];
#pragma unroll
        for (int c = 0; c < 32; c++)
            l[c] = fmaf(-0.5f, lr[c], __ldg(cj + c));

        float mx = l[0];
#pragma unroll
        for (int c = 1; c < 32; c++) mx = fmaxf(mx, l[c]);
        mx = fmaxf(mx, __shfl_xor_sync(0xffffffffu, mx, 1));

        float s = 0.0f;
#pragma unroll
        for (int c = 0; c < 32; c++) { l[c] = __expf(l[c] - mx); s += l[c]; }
        s += __shfl_xor_sync(0xffffffffu, s, 1);

        float inv = __fdividef(1.0f, s);
        if (grow < N) {
            float4* o4 = reinterpret_cast<float4*>(out + (size_t)grow * C_DIM + half * 32);
#pragma unroll
            for (int q = 0; q < 8; q++)
                o4[q] = make_float4(l[q * 4] * inv, l[q * 4 + 1] * inv,
                                    l[q * 4 + 2] * inv, l[q * 4 + 3] * inv);
        }
    }
}

// ---------------------------------------------------------------------------
extern "C" void kernel_launch(void* const* d_in, const int* in_sizes, int n_in,
                              void* d_out, int out_size) {
    const float* x       = (const float*)d_in[0];
    const float* mu      = (const float*)d_in[1];
    const float* log_var = (const float*)d_in[2];
    const float* beta    = (const float*)d_in[3];
    const float* njk     = (const float*)d_in[4];
    const float* alpha   = (const float*)d_in[5];
    const int*   macro   = (const int*)d_in[6];
    int N = in_sizes[0] / K_DIM;

    static bool attr_set = false;
    if (!attr_set) {
        cudaFuncSetAttribute(icgmm_mma_kernel,
                             cudaFuncAttributeMaxDynamicSharedMemorySize, SMEM_TOTAL);
        attr_set = true;
    }

    pre_kernel<<<C_DIM, 128>>>(mu, log_var, beta, njk, alpha);
    icgmm_mma_kernel<<<(N + TILE_M - 1) / TILE_M, NT, SMEM_TOTAL>>>(
        x, macro, (float*)d_out, N);
}